// round 6
// baseline (speedup 1.0000x reference)
#include <cuda_runtime.h>
#include <cuda_bf16.h>
#include <cstdint>

#define BATCH 4
#define HW    65536           // 256*256 pixels per (batch,channel)
#define KBINS 512             // 8^3 bins
#define GX    64              // 64 blocks * 1024 thr = exactly HW pixels
#define NTHR  1024
// -1 / (49 * 2*sigma^2), sigma = 0.02
#define NEG_COEF (-25.510204081632653f)
// tail truncation: far-bin relative weight at f=0.33 is exp(-25.51*0.34)=1.7e-4
#define TLO 0.33f
#define THI 0.67f

// Scratch (no cudaMalloc). Zero at module load; last block per batch resets
// it each run, preserving the invariant across graph replays.
__device__ float        g_hist[BATCH * KBINS];
__device__ unsigned int g_count[BATCH];

// Predicated shared-memory reduction: single @p RED.SHARED instruction,
// no BSSY/BSYNC branch pair (ptxas won't 0-BSSY a C++ if{} arm).
__device__ __forceinline__ void red_sh_pred(uint32_t addr, float val, bool pred) {
    asm volatile(
        "{\n\t"
        ".reg .pred p;\n\t"
        "setp.ne.u32 p, %2, 0;\n\t"
        "@p red.shared.add.f32 [%0], %1;\n\t"
        "}"
        :: "r"(addr), "f"(val), "r"((unsigned)pred) : "memory");
}

__global__ __launch_bounds__(NTHR, 2)
void dh_fused_kernel(const float* __restrict__ x, float* __restrict__ out) {
    __shared__ float sh[KBINS];     // block-private histogram
    __shared__ float red[32];
    __shared__ int   s_last;

    const int b   = blockIdx.y;
    const int tid = threadIdx.x;

    if (tid < KBINS) sh[tid] = 0.0f;
    __syncthreads();

    // exactly one pixel per thread, no bounds check, no range division
    const float* __restrict__ xb = x + (size_t)b * 3 * HW;
    const int p = blockIdx.x * NTHR + tid;

    {
        const float tx = __ldg(xb + p)          * 7.0f;
        const float ty = __ldg(xb + HW + p)     * 7.0f;
        const float tz = __ldg(xb + 2 * HW + p) * 7.0f;
        const int ix = min((int)tx, 6);
        const int iy = min((int)ty, 6);
        const int iz = min((int)tz, 6);
        const float fx = tx - (float)ix;
        const float fy = ty - (float)iy;
        const float fz = tz - (float)iz;
        const float gx = 1.0f - fx, gy = 1.0f - fy, gz = 1.0f - fz;

        const float wx0 = __expf(NEG_COEF * fx * fx);
        const float wx1 = __expf(NEG_COEF * gx * gx);
        const float wy0 = __expf(NEG_COEF * fy * fy);
        const float wy1 = __expf(NEG_COEF * gy * gy);
        float       wz0 = __expf(NEG_COEF * fz * fz);
        float       wz1 = __expf(NEG_COEF * gz * gz);

        // exact per-pixel normalizer (all 6 weights; +1e-8 matters)
        const float S   = (wx0 + wx1) * (wy0 + wy1) * (wz0 + wz1);
        const float inv = __fdividef(1.0f, S + 1e-8f);
        wz0 *= inv;
        wz1 *= inv;

        const bool px0 = fx < THI, px1 = fx > TLO;
        const bool py0 = fy < THI, py1 = fy > TLO;
        const bool pz0 = fz < THI, pz1 = fz > TLO;

        const float wyz00 = wy0 * wz0, wyz01 = wy0 * wz1;
        const float wyz10 = wy1 * wz0, wyz11 = wy1 * wz1;

        const uint32_t base =
            (uint32_t)__cvta_generic_to_shared(&sh[ix * 64 + iy * 8 + iz]);

        red_sh_pred(base +   0*4, wx0 * wyz00, px0 && py0 && pz0);
        red_sh_pred(base +   1*4, wx0 * wyz01, px0 && py0 && pz1);
        red_sh_pred(base +   8*4, wx0 * wyz10, px0 && py1 && pz0);
        red_sh_pred(base +   9*4, wx0 * wyz11, px0 && py1 && pz1);
        red_sh_pred(base +  64*4, wx1 * wyz00, px1 && py0 && pz0);
        red_sh_pred(base +  65*4, wx1 * wyz01, px1 && py0 && pz1);
        red_sh_pred(base +  72*4, wx1 * wyz10, px1 && py1 && pz0);
        red_sh_pred(base +  73*4, wx1 * wyz11, px1 && py1 && pz1);
    }

    __syncthreads();

    // flush block-private histogram: one bin per thread (tid < 512),
    // unconditional (most bins are hit; skip the branch)
    if (tid < KBINS) {
        atomicAdd(&g_hist[b * KBINS + tid], sh[tid]);
        __threadfence();    // only flushing warps pay the fence
    }

    // ---- last block per batch normalizes, writes out, resets scratch ----
    __syncthreads();
    if (tid == 0) {
        const unsigned t = atomicAdd(&g_count[b], 1u);
        s_last = (t == gridDim.x - 1) ? 1 : 0;
    }
    __syncthreads();

    if (s_last) {
        __threadfence();
        const float v = (tid < KBINS) ? __ldcg(&g_hist[b * KBINS + tid]) : 0.0f;

        float s = v;
        #pragma unroll
        for (int o = 16; o > 0; o >>= 1) s += __shfl_xor_sync(0xffffffffu, s, o);
        if ((tid & 31) == 0) red[tid >> 5] = s;
        __syncthreads();

        float total = 0.0f;
        #pragma unroll
        for (int k = 0; k < 32; ++k) total += red[k];

        if (tid < KBINS) {
            out[b * KBINS + tid] = v * __fdividef(1.0f, total + 1e-8f);
            // restore zero-invariant for the next graph replay
            g_hist[b * KBINS + tid] = 0.0f;
        }
        if (tid == 0) g_count[b] = 0u;
    }
}

extern "C" void kernel_launch(void* const* d_in, const int* in_sizes, int n_in,
                              void* d_out, int out_size) {
    const float* x = (const float*)d_in[0];
    float* out = (float*)d_out;

    dim3 grid(GX, BATCH);
    dh_fused_kernel<<<grid, NTHR>>>(x, out);
}

// round 7
// speedup vs baseline: 1.0476x; 1.0476x over previous
#include <cuda_runtime.h>
#include <cuda_bf16.h>
#include <cstdint>

#define BATCH 4
#define HW    65536           // 256*256 pixels per (batch,channel)
#define KBINS 512             // 8^3 bins
#define GX    74              // blocks/batch -> 296 CTAs = exactly 2/SM
#define NTHR  1024            // 2048 thr/SM = full occupancy
// -1 / (49 * 2*sigma^2), sigma = 0.02
#define NEG_COEF (-25.510204081632653f)
// tail truncation: far-bin relative weight at f=0.35 is exp(-25.51*0.30)=4.7e-4
#define TLO 0.35f
#define THI 0.65f

// Scratch (no cudaMalloc). Zero at module load; last block per batch resets
// it each run, preserving the invariant across graph replays.
__device__ float        g_hist[BATCH * KBINS];
__device__ unsigned int g_count[BATCH];

// Predicated shared-memory reduction: single @p RED.SHARED instruction,
// no BSSY/BSYNC branch pair.
__device__ __forceinline__ void red_sh_pred(uint32_t addr, float val, bool pred) {
    asm volatile(
        "{\n\t"
        ".reg .pred p;\n\t"
        "setp.ne.u32 p, %2, 0;\n\t"
        "@p red.shared.add.f32 [%0], %1;\n\t"
        "}"
        :: "r"(addr), "f"(val), "r"((unsigned)pred) : "memory");
}

__global__ __launch_bounds__(NTHR, 2)
void dh_fused_kernel(const float* __restrict__ x, float* __restrict__ out) {
    __shared__ float sh[KBINS];     // block-private histogram
    __shared__ float red[32];
    __shared__ int   s_last;

    const int b   = blockIdx.y;
    const int tid = threadIdx.x;

    if (tid < KBINS) sh[tid] = 0.0f;
    __syncthreads();

    // balanced contiguous range per block: 885 or 886 pixels (32-bit math)
    const float* __restrict__ xb = x + (size_t)b * 3 * HW;
    const int start = (int)(((unsigned)blockIdx.x       * HW) / GX);
    const int end   = (int)(((unsigned)(blockIdx.x + 1) * HW) / GX);
    const int p     = start + tid;

    if (p < end) {
        const float tx = __ldg(xb + p)          * 7.0f;
        const float ty = __ldg(xb + HW + p)     * 7.0f;
        const float tz = __ldg(xb + 2 * HW + p) * 7.0f;
        const int ix = min((int)tx, 6);
        const int iy = min((int)ty, 6);
        const int iz = min((int)tz, 6);
        const float fx = tx - (float)ix;
        const float fy = ty - (float)iy;
        const float fz = tz - (float)iz;
        const float gx = 1.0f - fx, gy = 1.0f - fy, gz = 1.0f - fz;

        const float wx0 = __expf(NEG_COEF * fx * fx);
        const float wx1 = __expf(NEG_COEF * gx * gx);
        const float wy0 = __expf(NEG_COEF * fy * fy);
        const float wy1 = __expf(NEG_COEF * gy * gy);
        float       wz0 = __expf(NEG_COEF * fz * fz);
        float       wz1 = __expf(NEG_COEF * gz * gz);

        // exact per-pixel normalizer (all 6 weights; +1e-8 matters)
        const float S   = (wx0 + wx1) * (wy0 + wy1) * (wz0 + wz1);
        const float inv = __fdividef(1.0f, S + 1e-8f);
        wz0 *= inv;
        wz1 *= inv;

        const bool px0 = fx < THI, px1 = fx > TLO;
        const bool py0 = fy < THI, py1 = fy > TLO;
        const bool pz0 = fz < THI, pz1 = fz > TLO;

        const float wyz00 = wy0 * wz0, wyz01 = wy0 * wz1;
        const float wyz10 = wy1 * wz0, wyz11 = wy1 * wz1;

        const uint32_t base =
            (uint32_t)__cvta_generic_to_shared(&sh[ix * 64 + iy * 8 + iz]);

        red_sh_pred(base +  0*4, wx0 * wyz00, px0 && py0 && pz0);
        red_sh_pred(base +  1*4, wx0 * wyz01, px0 && py0 && pz1);
        red_sh_pred(base +  8*4, wx0 * wyz10, px0 && py1 && pz0);
        red_sh_pred(base +  9*4, wx0 * wyz11, px0 && py1 && pz1);
        red_sh_pred(base + 64*4, wx1 * wyz00, px1 && py0 && pz0);
        red_sh_pred(base + 65*4, wx1 * wyz01, px1 && py0 && pz1);
        red_sh_pred(base + 72*4, wx1 * wyz10, px1 && py1 && pz0);
        red_sh_pred(base + 73*4, wx1 * wyz11, px1 && py1 && pz1);
    }

    __syncthreads();

    // flush block-private histogram: one bin per thread (tid < 512);
    // ~74 global adds per address -> no L2 serialization problem
    if (tid < KBINS) {
        atomicAdd(&g_hist[b * KBINS + tid], sh[tid]);
        __threadfence();    // only flushing warps pay the fence
    }

    // ---- last block per batch normalizes, writes out, resets scratch ----
    __syncthreads();
    if (tid == 0) {
        const unsigned t = atomicAdd(&g_count[b], 1u);
        s_last = (t == gridDim.x - 1) ? 1 : 0;
    }
    __syncthreads();

    if (s_last) {
        __threadfence();
        const float v = (tid < KBINS) ? __ldcg(&g_hist[b * KBINS + tid]) : 0.0f;

        float s = v;
        #pragma unroll
        for (int o = 16; o > 0; o >>= 1) s += __shfl_xor_sync(0xffffffffu, s, o);
        if ((tid & 31) == 0) red[tid >> 5] = s;
        __syncthreads();

        float total = 0.0f;
        #pragma unroll
        for (int k = 0; k < 32; ++k) total += red[k];

        if (tid < KBINS) {
            out[b * KBINS + tid] = v * __fdividef(1.0f, total + 1e-8f);
            // restore zero-invariant for the next graph replay
            g_hist[b * KBINS + tid] = 0.0f;
        }
        if (tid == 0) g_count[b] = 0u;
    }
}

extern "C" void kernel_launch(void* const* d_in, const int* in_sizes, int n_in,
                              void* d_out, int out_size) {
    const float* x = (const float*)d_in[0];
    float* out = (float*)d_out;

    dim3 grid(GX, BATCH);
    dh_fused_kernel<<<grid, NTHR>>>(x, out);
}